// round 17
// baseline (speedup 1.0000x reference)
#include <cuda_runtime.h>
#include <cuda_fp16.h>
#include <cstdint>

#define NTOK 4096
#define HDIM 1024
#define FDIM 2048
#define EXPE 8
#define NPAIR (NTOK * 2)

// ================= scratch (static device globals) =================
__device__ __half g_xh[(size_t)NTOK * HDIM];
// fp16 weights in NATURAL layout (no transpose):
__device__ __half g_wu16[(size_t)EXPE * HDIM * FDIM]; // [E][H][F]
__device__ __half g_wg16[(size_t)EXPE * HDIM * FDIM]; // [E][H][F]
__device__ __half g_wd16[(size_t)EXPE * FDIM * HDIM]; // [E][F][H]
__device__ __half g_phi[(size_t)NPAIR * FDIM];
__device__ int   g_cnt[EXPE];
__device__ int   g_off[EXPE + 1];
__device__ int   g_cur[EXPE];
__device__ int   g_tok_e[NTOK * 2];
__device__ float g_tok_w[NTOK * 2];
__device__ int   g_row_tok[NPAIR];
__device__ float g_row_w[NPAIR];

__device__ __forceinline__ uint32_t smem_u32(const void* p) {
    uint32_t a;
    asm("{ .reg .u64 t; cvta.to.shared.u64 t, %1; cvt.u32.u64 %0, t; }"
        : "=r"(a) : "l"(p));
    return a;
}

// mma.sync fp16 in / fp32 acc (sm_80+ baseline PTX)
#define MMA_F16(acc, a, b0, b1)                                                 \
    asm volatile(                                                               \
        "mma.sync.aligned.m16n8k16.row.col.f32.f16.f16.f32 "                    \
        "{%0,%1,%2,%3}, {%4,%5,%6,%7}, {%8,%9}, {%0,%1,%2,%3};"                 \
        : "+f"((acc)[0]), "+f"((acc)[1]), "+f"((acc)[2]), "+f"((acc)[3])        \
        : "r"((a)[0]), "r"((a)[1]), "r"((a)[2]), "r"((a)[3]), "r"(b0), "r"(b1))

#define LDMX4(r, addr)                                                          \
    asm volatile("ldmatrix.sync.aligned.m8n8.x4.shared.b16 {%0,%1,%2,%3}, [%4];"\
        : "=r"((r)[0]), "=r"((r)[1]), "=r"((r)[2]), "=r"((r)[3]) : "r"(addr))

// transposed ldmatrix: col-major B fragments from [k][n] row-major smem
#define LDMX4T(r, addr)                                                         \
    asm volatile("ldmatrix.sync.aligned.m8n8.x4.trans.shared.b16 "              \
                 "{%0,%1,%2,%3}, [%4];"                                         \
        : "=r"((r)[0]), "=r"((r)[1]), "=r"((r)[2]), "=r"((r)[3]) : "r"(addr))

#define CP_ASYNC16(sm, gp)                                                      \
    asm volatile("cp.async.cg.shared.global [%0], [%1], 16;"                    \
                 :: "r"(sm), "l"(gp))
#define CP_COMMIT() asm volatile("cp.async.commit_group;" ::: "memory")
#define CP_WAIT1()  asm volatile("cp.async.wait_group 1;" ::: "memory")
#define CP_WAIT0()  asm volatile("cp.async.wait_group 0;" ::: "memory")

__device__ __forceinline__ uint32_t pack2(float a, float b) {
    __half2 h = __floats2half2_rn(a, b);
    return *reinterpret_cast<uint32_t*>(&h);
}

// ================= 0) init =================
__global__ void init_kernel(float* __restrict__ out) {
    int tid = blockIdx.x * blockDim.x + threadIdx.x;
    if (tid < EXPE) g_cnt[tid] = 0;
    const int total = NTOK * HDIM;
    for (int i = tid * 4; i < total; i += gridDim.x * blockDim.x * 4)
        *reinterpret_cast<float4*>(out + i) = make_float4(0.f, 0.f, 0.f, 0.f);
}

// ================= 1) router =================
__global__ void router_kernel(const float* __restrict__ x,
                              const float* __restrict__ gw,
                              float* __restrict__ rl_out) {
    __shared__ float sgw[EXPE * HDIM];
    int tid = threadIdx.x;
    for (int i = tid; i < EXPE * HDIM; i += 128) sgw[i] = gw[i];
    __syncthreads();

    int warp = tid >> 5, lane = tid & 31;
    int n = blockIdx.x * 4 + warp;
    if (n >= NTOK) return;
    const float* xr = x + (size_t)n * HDIM;

    float acc[EXPE];
#pragma unroll
    for (int e = 0; e < EXPE; e++) acc[e] = 0.f;
    for (int h = lane; h < HDIM; h += 32) {
        float xv = xr[h];
#pragma unroll
        for (int e = 0; e < EXPE; e++) acc[e] += xv * sgw[e * HDIM + h];
    }
#pragma unroll
    for (int e = 0; e < EXPE; e++)
#pragma unroll
        for (int o = 16; o > 0; o >>= 1)
            acc[e] += __shfl_xor_sync(0xffffffffu, acc[e], o);

    if (lane == 0) {
#pragma unroll
        for (int e = 0; e < EXPE; e++) rl_out[(size_t)n * EXPE + e] = acc[e];
        float m = acc[0];
#pragma unroll
        for (int e = 1; e < EXPE; e++) m = fmaxf(m, acc[e]);
        float p[EXPE];
#pragma unroll
        for (int e = 0; e < EXPE; e++) p[e] = __expf(acc[e] - m);
        int i0 = 0;
#pragma unroll
        for (int e = 1; e < EXPE; e++) if (p[e] > p[i0]) i0 = e;
        int i1 = (i0 == 0) ? 1 : 0;
#pragma unroll
        for (int e = 0; e < EXPE; e++)
            if (e != i0 && p[e] > p[i1]) i1 = e;
        float s2 = p[i0] + p[i1];
        g_tok_e[n * 2 + 0] = i0; g_tok_w[n * 2 + 0] = p[i0] / s2;
        g_tok_e[n * 2 + 1] = i1; g_tok_w[n * 2 + 1] = p[i1] / s2;
        atomicAdd(&g_cnt[i0], 1);
        atomicAdd(&g_cnt[i1], 1);
    }
}

// ================= 2) scan =================
__global__ void scan_kernel() {
    if (threadIdx.x == 0 && blockIdx.x == 0) {
        int acc = 0;
        for (int e = 0; e < EXPE; e++) {
            g_off[e] = acc; g_cur[e] = acc; acc += g_cnt[e];
        }
        g_off[EXPE] = acc;
    }
}

// ================= 3) scatter =================
__global__ void scatter_kernel() {
    int n = blockIdx.x * blockDim.x + threadIdx.x;
    if (n >= NTOK) return;
#pragma unroll
    for (int k = 0; k < 2; k++) {
        int e = g_tok_e[n * 2 + k];
        int pos = atomicAdd(&g_cur[e], 1);
        g_row_tok[pos] = n;
        g_row_w[pos] = g_tok_w[n * 2 + k];
    }
}

// ================= 4) convert x to fp16 =================
__global__ void cvt_x_kernel(const float* __restrict__ x) {
    int i = blockIdx.x * blockDim.x + threadIdx.x;
    float4 v = reinterpret_cast<const float4*>(x)[i];
    uint2 o;
    o.x = pack2(v.x, v.y);
    o.y = pack2(v.z, v.w);
    reinterpret_cast<uint2*>(g_xh)[i] = o;
}

// ================= 5) straight fp32->fp16 weight convert ==============
// No transpose needed anymore (ldmatrix.trans in the GEMMs).
// Destinations bound in device code (round-8 ATS lesson).
__global__ void cvt_w_kernel(const float* __restrict__ src, int which) {
    __half* dst;
    if (which == 0)      dst = g_wu16;
    else if (which == 1) dst = g_wg16;
    else                 dst = g_wd16;
    int i = blockIdx.x * blockDim.x + threadIdx.x;
    float4 v = reinterpret_cast<const float4*>(src)[i];
    uint2 o;
    o.x = pack2(v.x, v.y);
    o.y = pack2(v.z, v.w);
    reinterpret_cast<uint2*>(dst)[i] = o;
}

// ================= 6) up+gate mma.sync GEMM =================
// block: 128 rows x 64 f, BK=64. 8 warps: 4 (m) x 2 (n). warp tile 32x32.
// A smem [128][SA], B smem [64 k][SB] per matrix (rows = contiguous gmem).
#define SA 72
#define SB 72
#define UG_A_BYTES (128 * SA * 2)          // 18432
#define UG_B_BYTES (64 * SB * 2)           // 9216
#define UG_BUF (UG_A_BYTES + 2 * UG_B_BYTES)  // 36864
#define UG_DSM (2 * UG_BUF)                // 73728

__global__ __launch_bounds__(256) void up_gate_mma(
    const float* __restrict__ b_up, const float* __restrict__ b_gate) {
    extern __shared__ char dynsm[];
    __shared__ int toks[128];

    int e = blockIdx.y >> 5;
    int t = blockIdx.y & 31;
    int cnt = g_cnt[e];
    int m0 = t * 128;
    if (m0 >= cnt) return;
    int base = g_off[e] + m0;
    int valid = min(128, cnt - m0);
    int f0 = blockIdx.x * 64;

    int tid = threadIdx.x;
    if (tid < 128) toks[tid] = g_row_tok[base + min(tid, valid - 1)];
    __syncthreads();

    const __half* WU = g_wu16 + (size_t)e * HDIM * FDIM;  // [H][F]
    const __half* WG = g_wg16 + (size_t)e * HDIM * FDIM;

    int wid = tid >> 5, lane = tid & 31;
    int wm = wid & 3, wn = wid >> 2;
    int grp = lane >> 2, qid = lane & 3;

    uint32_t dynB = smem_u32(dynsm);
    // A (non-trans) fragment addressing
    int arow = wm * 32 + (lane & 15);
    int acol8 = (lane >> 4) * 8;
    // B (trans) fragment addressing: [k][n] tile
    int bg = lane >> 3, brr = lane & 7;
    int b_row16 = ((bg & 1) << 3) + brr;   // row within 16-k group
    int b_col8 = (bg >> 1) << 3;           // 0 or 8

    auto stage = [&](int buf, int k0) {
        uint32_t db = dynB + buf * UG_BUF;
        // A: 128 rows x 64 k; 8 segs/row, 4 per thread
#pragma unroll
        for (int i = 0; i < 4; i++) {
            int u = tid + i * 256;
            int r = u >> 3, sg = u & 7;
            size_t src = (size_t)toks[r] * HDIM + k0 + sg * 8;
            CP_ASYNC16(db + (uint32_t)((r * SA + sg * 8) * 2), g_xh + src);
        }
        // B: 64 k-rows x 64 f (rows contiguous in gmem); 2 per thread per matrix
#pragma unroll
        for (int i = 0; i < 2; i++) {
            int u = tid + i * 256;
            int r = u >> 3, sg = u & 7;
            size_t wo = (size_t)(k0 + r) * FDIM + f0 + sg * 8;
            uint32_t so = (uint32_t)((r * SB + sg * 8) * 2);
            CP_ASYNC16(db + UG_A_BYTES + so,              WU + wo);
            CP_ASYNC16(db + UG_A_BYTES + UG_B_BYTES + so, WG + wo);
        }
    };

    float accU[2][4][4], accG[2][4][4];
#pragma unroll
    for (int a = 0; a < 2; a++)
#pragma unroll
        for (int b = 0; b < 4; b++)
#pragma unroll
            for (int c = 0; c < 4; c++) { accU[a][b][c] = 0.f; accG[a][b][c] = 0.f; }

    const int NIT = HDIM / 64;   // 16
    stage(0, 0);
    CP_COMMIT();

    for (int it = 0; it < NIT; it++) {
        if (it + 1 < NIT) {
            stage((it + 1) & 1, (it + 1) * 64);
            CP_COMMIT();
            CP_WAIT1();
        } else {
            CP_WAIT0();
        }
        __syncthreads();

        uint32_t db = dynB + (it & 1) * UG_BUF;
        uint32_t AB = db, UB = db + UG_A_BYTES, GB = db + UG_A_BYTES + UG_B_BYTES;

#pragma unroll
        for (int ks = 0; ks < 4; ks++) {
            uint32_t ah[2][4];
#pragma unroll
            for (int mf = 0; mf < 2; mf++) {
                uint32_t ao = (uint32_t)(((arow + mf * 16) * SA + ks * 16 + acol8) * 2);
                LDMX4(ah[mf], AB + ao);
            }
            uint32_t uh[8], gh[8];
#pragma unroll
            for (int p = 0; p < 2; p++) {
                uint32_t bo = (uint32_t)(((ks * 16 + b_row16) * SB +
                                          wn * 32 + p * 16 + b_col8) * 2);
                LDMX4T(uh + p * 4, UB + bo);
                LDMX4T(gh + p * 4, GB + bo);
            }
#pragma unroll
            for (int nf = 0; nf < 4; nf++) {
                uint32_t u0 = uh[nf * 2], u1 = uh[nf * 2 + 1];
                uint32_t g0 = gh[nf * 2], g1 = gh[nf * 2 + 1];
#pragma unroll
                for (int mf = 0; mf < 2; mf++) {
                    MMA_F16(accU[mf][nf], ah[mf], u0, u1);
                    MMA_F16(accG[mf][nf], ah[mf], g0, g1);
                }
            }
        }
        __syncthreads();
    }

    // epilogue: phi = silu(v)*u, single fp16
#pragma unroll
    for (int mf = 0; mf < 2; mf++) {
#pragma unroll
        for (int half = 0; half < 2; half++) {
            int mloc = wm * 32 + mf * 16 + grp + half * 8;
            if (mloc >= valid) continue;
            size_t row = (size_t)(base + mloc);
#pragma unroll
            for (int nf = 0; nf < 4; nf++) {
                int fc = f0 + wn * 32 + nf * 8 + qid * 2;
                float u0 = accU[mf][nf][half * 2 + 0] + __ldg(b_up + e * FDIM + fc);
                float u1 = accU[mf][nf][half * 2 + 1] + __ldg(b_up + e * FDIM + fc + 1);
                float v0 = accG[mf][nf][half * 2 + 0] + __ldg(b_gate + e * FDIM + fc);
                float v1 = accG[mf][nf][half * 2 + 1] + __ldg(b_gate + e * FDIM + fc + 1);
                float p0 = (v0 / (1.f + __expf(-v0))) * u0;
                float p1 = (v1 / (1.f + __expf(-v1))) * u1;
                *reinterpret_cast<uint32_t*>(g_phi + row * FDIM + fc) = pack2(p0, p1);
            }
        }
    }
}

// ================= 7) down mma.sync GEMM + combine =================
// block: 128 rows x 128 h, BK=64. 8 warps: 2 (m) x 4 (n). warp tile 64x32.
#define SD 136
#define DN_A_BYTES (128 * SA * 2)          // 18432
#define DN_B_BYTES (64 * SD * 2)           // 17408
#define DN_BUF (DN_A_BYTES + DN_B_BYTES)   // 35840
#define DN_DSM (2 * DN_BUF)                // 71680

__global__ __launch_bounds__(256) void down_mma(
    const float* __restrict__ b_down, float* __restrict__ out) {
    extern __shared__ char dynsm[];
    __shared__ int   toks[128];
    __shared__ float rws[128];

    int e = blockIdx.y >> 5;
    int t = blockIdx.y & 31;
    int cnt = g_cnt[e];
    int m0 = t * 128;
    if (m0 >= cnt) return;
    int base = g_off[e] + m0;
    int valid = min(128, cnt - m0);
    int h0 = blockIdx.x * 128;

    int tid = threadIdx.x;
    if (tid < 128) {
        int r = base + min(tid, valid - 1);
        toks[tid] = g_row_tok[r];
        rws[tid]  = g_row_w[r];
    }
    __syncthreads();

    const __half* WD = g_wd16 + (size_t)e * FDIM * HDIM;  // [F][H]

    int wid = tid >> 5, lane = tid & 31;
    int wm = wid & 1, wn = wid >> 1;
    int grp = lane >> 2, qid = lane & 3;

    uint32_t dynB = smem_u32(dynsm);
    int arow = wm * 64 + (lane & 15);
    int acol8 = (lane >> 4) * 8;
    int bg = lane >> 3, brr = lane & 7;
    int b_row16 = ((bg & 1) << 3) + brr;
    int b_col8 = (bg >> 1) << 3;

    auto stage = [&](int buf, int k0) {
        uint32_t db = dynB + buf * DN_BUF;
        // A: phi 128 rows x 64 k; 4 per thread
#pragma unroll
        for (int i = 0; i < 4; i++) {
            int u = tid + i * 256;
            int r = u >> 3, sg = u & 7;
            size_t src = (size_t)(base + min(r, valid - 1)) * FDIM + k0 + sg * 8;
            CP_ASYNC16(db + (uint32_t)((r * SA + sg * 8) * 2), g_phi + src);
        }
        // B: 64 f-rows x 128 h (rows contiguous); 16 segs/row, 4 per thread
#pragma unroll
        for (int i = 0; i < 4; i++) {
            int u = tid + i * 256;
            int r = u >> 4, sg = u & 15;
            size_t wo = (size_t)(k0 + r) * HDIM + h0 + sg * 8;
            CP_ASYNC16(db + DN_A_BYTES + (uint32_t)((r * SD + sg * 8) * 2), WD + wo);
        }
    };

    float acc[4][4][4];
#pragma unroll
    for (int a = 0; a < 4; a++)
#pragma unroll
        for (int b = 0; b < 4; b++)
#pragma unroll
            for (int c = 0; c < 4; c++) acc[a][b][c] = 0.f;

    const int NIT = FDIM / 64;   // 32
    stage(0, 0);
    CP_COMMIT();

    for (int it = 0; it < NIT; it++) {
        if (it + 1 < NIT) {
            stage((it + 1) & 1, (it + 1) * 64);
            CP_COMMIT();
            CP_WAIT1();
        } else {
            CP_WAIT0();
        }
        __syncthreads();

        uint32_t db = dynB + (it & 1) * DN_BUF;
        uint32_t AB = db, BB = db + DN_A_BYTES;

#pragma unroll
        for (int ks = 0; ks < 4; ks++) {
            uint32_t ah[4][4];
#pragma unroll
            for (int mf = 0; mf < 4; mf++) {
                uint32_t ao = (uint32_t)(((arow + mf * 16) * SA + ks * 16 + acol8) * 2);
                LDMX4(ah[mf], AB + ao);
            }
            uint32_t bh[8];
#pragma unroll
            for (int p = 0; p < 2; p++) {
                uint32_t bo = (uint32_t)(((ks * 16 + b_row16) * SD +
                                          wn * 32 + p * 16 + b_col8) * 2);
                LDMX4T(bh + p * 4, BB + bo);
            }
#pragma unroll
            for (int nf = 0; nf < 4; nf++) {
                uint32_t b0 = bh[nf * 2], b1 = bh[nf * 2 + 1];
#pragma unroll
                for (int mf = 0; mf < 4; mf++)
                    MMA_F16(acc[mf][nf], ah[mf], b0, b1);
            }
        }
        __syncthreads();
    }

    // epilogue: out[token] += w * (acc + b_down)
#pragma unroll
    for (int mf = 0; mf < 4; mf++) {
#pragma unroll
        for (int half = 0; half < 2; half++) {
            int mloc = wm * 64 + mf * 16 + grp + half * 8;
            if (mloc >= valid) continue;
            int token = toks[mloc];
            float w = rws[mloc];
            float* orow = out + (size_t)token * HDIM;
#pragma unroll
            for (int nf = 0; nf < 4; nf++) {
                int hc = h0 + wn * 32 + nf * 8 + qid * 2;
                float y0 = acc[mf][nf][half * 2 + 0] + __ldg(b_down + e * HDIM + hc);
                float y1 = acc[mf][nf][half * 2 + 1] + __ldg(b_down + e * HDIM + hc + 1);
                atomicAdd(orow + hc,     w * y0);
                atomicAdd(orow + hc + 1, w * y1);
            }
        }
    }
}

// ================= launch =================
extern "C" void kernel_launch(void* const* d_in, const int* in_sizes, int n_in,
                              void* d_out, int out_size) {
    const float* x      = (const float*)d_in[0];
    const float* gate_w = (const float*)d_in[1];
    const float* w_up   = (const float*)d_in[2];
    const float* w_gate = (const float*)d_in[3];
    const float* w_down = (const float*)d_in[4];
    const float* b_up   = (const float*)d_in[5];
    const float* b_gate = (const float*)d_in[6];
    const float* b_down = (const float*)d_in[7];

    float* out = (float*)d_out;
    float* rl  = out + (size_t)NTOK * HDIM;

    cudaFuncSetAttribute(up_gate_mma,
                         cudaFuncAttributeMaxDynamicSharedMemorySize, UG_DSM);
    cudaFuncSetAttribute(down_mma,
                         cudaFuncAttributeMaxDynamicSharedMemorySize, DN_DSM);

    init_kernel<<<1024, 256>>>(out);
    router_kernel<<<NTOK / 4, 128>>>(x, gate_w, rl);
    scan_kernel<<<1, 32>>>();
    scatter_kernel<<<NTOK / 256, 256>>>();

    cvt_x_kernel<<<(NTOK * HDIM / 4) / 256, 256>>>(x);
    {
        const int WELEMS = EXPE * HDIM * FDIM;     // 16M per tensor
        cvt_w_kernel<<<(WELEMS / 4) / 256, 256>>>(w_up,   0);
        cvt_w_kernel<<<(WELEMS / 4) / 256, 256>>>(w_gate, 1);
        cvt_w_kernel<<<(WELEMS / 4) / 256, 256>>>(w_down, 2);
    }

    dim3 gridA(FDIM / 64, EXPE * 32);
    up_gate_mma<<<gridA, 256, UG_DSM>>>(b_up, b_gate);

    dim3 gridB(HDIM / 128, EXPE * 32);
    down_mma<<<gridB, 256, DN_DSM>>>(b_down, out);
}